// round 12
// baseline (speedup 1.0000x reference)
#include <cuda_runtime.h>
#include <cuda_bf16.h>

#define NB 128
#define THREADS 384            // 12 warps = 3 per SMSP; 192 KB private slab
#define CHUNKS 6               // 24 slices * 6 = 144 blocks ~ one wave on 148 SMs
#define SLICE_F4 16384         // 65536 pixels per (B,C) slice
#define CHUNK_F4 2731          // ceil(16384/6); <= 8 per thread -> two unroll-4 batches
#define MAX_SLICES 32

#define HW 0.00390625f         // half bin width = 1/256 (exact)
#define BIN_W 0.0078125f       // 1/128
#define LN101 0.009950330853155723f
#define INV_N 1.52587890625e-05f   // 1/65536

// partials: [slice][chunk][bin]; ticket counters reset by the last block each launch
__device__ float g_part[MAX_SLICES * CHUNKS * NB];
__device__ unsigned g_cnt[MAX_SLICES];

// x*128 is EXACT in fp32 (x in [0,1)) -> trunc is the true bin; centers
// (2b+1)/256 and d are exact vs the jnp reference. fma(d,ln101,1) > 1
// reproduces the reference's fp32 pow rounding cutoff
// (validated round 4: rel_err 6.7e-8 — math frozen).
// Sentinel x = -1: (int)(-128.0f) & 127 == 0, d < 0 -> y = 0 (no contribution).
__device__ __forceinline__ void acc(float x, float* __restrict__ H, int tid) {
    float tf = x * 128.0f;
    int b = ((int)tf) & 127;                  // &127 bounds smem indexing
    float c = fmaf((float)b, BIN_W, HW);      // exact (2b+1)/256
    float d = HW - fabsf(x - c);
    float y = fmaf(d, LN101, 1.0f);
    y = (y > 1.0f) ? y : 0.0f;                // threshold (covers exact-edge d<=0)
    float* p = &H[b * THREADS + tid];         // bank = tid mod 32: conflict-free
    *p = *p + y;                              // single-writer RMW
}

__device__ __forceinline__ void acc4(float4 v, float* __restrict__ H, int tid) {
    acc(v.x, H, tid); acc(v.y, H, tid); acc(v.z, H, tid); acc(v.w, H, tid);
}

__global__ void __launch_bounds__(THREADS, 1) hist_kernel(const float* __restrict__ in,
                                                          float* __restrict__ out) {
    extern __shared__ float sh[];              // 128 * 384 * 4B = 192 KB
    const int tid = threadIdx.x;
    const int chunk = blockIdx.x;
    const int slice = blockIdx.y;

    // zero private histograms: 32 STS.128 per thread, coalesced, conflict-free
    {
        float4 z = make_float4(0.f, 0.f, 0.f, 0.f);
        float4* sh4 = (float4*)sh;
#pragma unroll
        for (int q = 0; q < (NB * THREADS / 4) / THREADS; q++)
            sh4[q * THREADS + tid] = z;
    }
    __syncthreads();

    const float4* p = (const float4*)in + (size_t)slice * SLICE_F4;
    const int start = chunk * CHUNK_F4;
    const int end = min(start + CHUNK_F4, SLICE_F4);
    const float4 sent = make_float4(-1.f, -1.f, -1.f, -1.f);

    // straight-line main body: 2 batches of 4 front-batched LDG.128 (MLP=4).
    // Batch 1 is always in-bounds: tid + 3*384 = 1535 < 2729 <= chunk length.
    const int i0 = start + tid;
    {
        float4 v0 = p[i0 + 0 * THREADS];
        float4 v1 = p[i0 + 1 * THREADS];
        float4 v2 = p[i0 + 2 * THREADS];
        float4 v3 = p[i0 + 3 * THREADS];
        acc4(v0, sh, tid);
        acc4(v1, sh, tid);
        acc4(v2, sh, tid);
        acc4(v3, sh, tid);
    }
    // Batch 2: sentinel-guarded (covers up to 8 per-thread elements = ceil(2731/384))
    {
        const int j = i0 + 4 * THREADS;
        float4 v0 = (j + 0 * THREADS < end) ? p[j + 0 * THREADS] : sent;
        float4 v1 = (j + 1 * THREADS < end) ? p[j + 1 * THREADS] : sent;
        float4 v2 = (j + 2 * THREADS < end) ? p[j + 2 * THREADS] : sent;
        float4 v3 = (j + 3 * THREADS < end) ? p[j + 3 * THREADS] : sent;
        acc4(v0, sh, tid);
        acc4(v1, sh, tid);
        acc4(v2, sh, tid);
        acc4(v3, sh, tid);
    }
    __syncthreads();

    // reduce: 3 threads per bin (part = tid>>7); scalar staggered reads are
    // conflict-free (row starts all bank-0 since 384 % 32 == 0).
    float sum;
    {
        const int bin = tid & 127;
        const int part = tid >> 7;             // 0..2
        const float* R = sh + bin * THREADS + part * NB;
        float s0 = 0.f, s1 = 0.f, s2 = 0.f, s3 = 0.f;
#pragma unroll 8
        for (int k = 0; k < NB; k += 4) {
            s0 += R[(k + 0 + tid) & 127];
            s1 += R[(k + 1 + tid) & 127];
            s2 += R[(k + 2 + tid) & 127];
            s3 += R[(k + 3 + tid) & 127];
        }
        sum = (s0 + s1) + (s2 + s3);
    }
    __syncthreads();                  // all reads of sh done before overwrite
    sh[tid] = sum;                    // sh[part*128 + bin]
    __syncthreads();

    // write this block's 128 partials, then take a ticket
    if (tid < NB) {
        float t = sh[tid] + sh[tid + NB] + sh[tid + 2 * NB];
        __stcg(&g_part[(slice * CHUNKS + chunk) * NB + tid], t);
    }
    __threadfence();
    __syncthreads();

    __shared__ unsigned s_ticket;
    if (tid == 0) s_ticket = atomicAdd(&g_cnt[slice], 1u);
    __syncthreads();

    if (s_ticket == CHUNKS - 1) {     // last block of this slice: final reduce
        __threadfence();              // acquire side: order partial reads after ticket
        if (tid < NB) {
            float t = 0.f;
#pragma unroll
            for (int c = 0; c < CHUNKS; c++)
                t += __ldcg(&g_part[(slice * CHUNKS + c) * NB + tid]);
            out[slice * NB + tid] = t * INV_N;
        }
        if (tid == 0) atomicExch(&g_cnt[slice], 0u);   // reset for next replay
    }
}

extern "C" void kernel_launch(void* const* d_in, const int* in_sizes, int n_in,
                              void* d_out, int out_size) {
    const float* in = (const float*)d_in[0];
    float* out = (float*)d_out;

    const int n_pixels = in_sizes[0];
    const int n_slices = n_pixels / (SLICE_F4 * 4);   // B*C = 24

    const int smem = NB * THREADS * (int)sizeof(float);   // 196608
    cudaFuncSetAttribute(hist_kernel, cudaFuncAttributeMaxDynamicSharedMemorySize, smem);

    dim3 grid(CHUNKS, n_slices);
    hist_kernel<<<grid, THREADS, smem>>>(in, out);
}